// round 9
// baseline (speedup 1.0000x reference)
#include <cuda_runtime.h>
#include <stdint.h>

#define VOCAB 512
#define WCHARS 24
#define WPB 8          // warps per block

// Two-node graph:
//   node 1: cudaMemsetAsync zeroes the whole output (fast dense-fill path,
//           no SM involvement)
//   node 2: this kernel scatters <=24 weighted RED.ADD.F32 per row and
//           writes the (lengths) tail. Ordering is via the graph edge.
// int64 inputs arrive as int32 (jax x64 disabled).
__global__ void __launch_bounds__(WPB * 32)
fofe_scatter_kernel(const int* __restrict__ sents,
                    const int* __restrict__ lengths,
                    const float* __restrict__ alpha_p,
                    float* __restrict__ out,
                    int nrows,
                    long long main_elems,
                    int extra,
                    int nlen)
{
    const int warp = threadIdx.x >> 5;
    const int lane = threadIdx.x & 31;
    const int row  = blockIdx.x * WPB + warp;

    // tail: (out, lengths) second output appended to d_out (overwrites zeros)
    if (blockIdx.x == 0 && (int)threadIdx.x < extra) {
        int i = threadIdx.x;
        out[main_elems + i] = (i < nlen) ? (float)lengths[i] : 0.0f;
    }
    if (row >= nrows) return;

    int c = 0;
    if (lane < WCHARS)
        c = sents[(long long)row * WCHARS + lane];
    const float a = __ldg(alpha_p);

    const bool valid = (lane < WCHARS) && (c > 0) && (c < VOCAB);
    const unsigned nz = __ballot_sync(0xffffffffu, valid);

    if (valid) {
        // # of nonzero chars strictly after this lane
        const int suffix = __popc(nz & (0xfffffffeu << lane));
        const float w = (suffix == 0) ? 1.0f
                                      : exp2f(log2f(a) * (float)suffix);
        // fire-and-forget global reduction (RED.ADD.F32), mostly spread addrs
        atomicAdd(&out[(long long)row * VOCAB + c], w);
    }
}

extern "C" void kernel_launch(void* const* d_in, const int* in_sizes, int n_in,
                              void* d_out, int out_size)
{
    const int*   sents   = (const int*)d_in[0];
    const int*   lengths = (const int*)d_in[1];
    const float* alpha   = (const float*)d_in[2];
    float*       out     = (float*)d_out;

    const int nrows = in_sizes[0] / WCHARS;             // B*S = 32768
    const long long main_elems = (long long)nrows * VOCAB;
    const int nlen = in_sizes[1];

    long long extra_ll = (long long)out_size - main_elems;
    if (extra_ll < 0) extra_ll = 0;
    if (extra_ll > WPB * 32) extra_ll = WPB * 32;

    // node 1: dense zero-fill of the entire output buffer (graph memset node)
    cudaMemsetAsync(d_out, 0, (size_t)out_size * sizeof(float), 0);

    // node 2: scatter the weighted contributions + tail
    const int blocks = (nrows + WPB - 1) / WPB;
    fofe_scatter_kernel<<<blocks, WPB * 32>>>(sents, lengths, alpha, out,
                                              nrows, main_elems,
                                              (int)extra_ll, nlen);
}

// round 10
// speedup vs baseline: 1.2745x; 1.2745x over previous
#include <cuda_runtime.h>
#include <stdint.h>

#define VOCAB 512
#define WCHARS 24
#define WPB 8          // warps per block == rows per block

// Hybrid drain: all blocks build per-warp 512-bin smem histograms the same
// way; EVEN blocks stream them out with LDS->STG.128 (L1/LSU store path),
// ODD blocks drain with a single 16KB TMA bulk copy (TMA engine reads smem
// directly). The two drain paths use disjoint hardware and overlap.
// Tail output (lengths) fused into block 0. int64 inputs arrive as int32
// (jax x64 disabled).
__global__ void __launch_bounds__(WPB * 32)
fofe_kernel(const int* __restrict__ sents,
            const int* __restrict__ lengths,
            const float* __restrict__ alpha_p,
            float* __restrict__ out,
            int nrows,
            long long main_elems,
            int extra,
            int nlen)
{
    __shared__ __align__(128) float hist[WPB][VOCAB];   // 16 KB, block-contiguous

    const int warp = threadIdx.x >> 5;
    const int lane = threadIdx.x & 31;
    const int row0 = blockIdx.x * WPB;
    const int row  = row0 + warp;
    const int rows_here = min(WPB, nrows - row0);

    // fused tail: (out, lengths) second output appended to d_out
    if (blockIdx.x == 0 && (int)threadIdx.x < extra) {
        int i = threadIdx.x;
        out[main_elems + i] = (i < nlen) ? (float)lengths[i] : 0.0f;
    }

    // ---- common front-end: build the histogram ----
    if (warp < rows_here) {
        float* h = hist[warp];

        // input load first; zero-fill overlaps its latency
        int c = 0;
        if (lane < WCHARS)
            c = sents[(long long)row * WCHARS + lane];
        const float a = __ldg(alpha_p);

        float4* h4 = reinterpret_cast<float4*>(h);
        const float4 z = make_float4(0.f, 0.f, 0.f, 0.f);
        #pragma unroll
        for (int j = 0; j < 4; ++j)
            h4[j * 32 + lane] = z;

        const bool valid = (lane < WCHARS) && (c > 0) && (c < VOCAB);
        const unsigned nz = __ballot_sync(0xffffffffu, valid);
        __syncwarp();                       // zeros visible before atomics

        if (valid) {
            const int suffix = __popc(nz & (0xfffffffeu << lane));
            const float w = (suffix == 0) ? 1.0f
                                          : exp2f(log2f(a) * (float)suffix);
            atomicAdd(&h[c], w);            // shared atomic, <=24 per row
        }
    }

    if (blockIdx.x & 1) {
        // ---- TMA drain: one 16KB bulk copy for the whole block ----
        __syncthreads();                    // all 8 histograms complete
        if (threadIdx.x == 0) {
            asm volatile("fence.proxy.async.shared::cta;" ::: "memory");
            unsigned saddr = (unsigned)__cvta_generic_to_shared(&hist[0][0]);
            float*   gdst  = out + (long long)row0 * VOCAB;
            unsigned bytes = (unsigned)rows_here * VOCAB * sizeof(float);
            asm volatile(
                "cp.async.bulk.global.shared::cta.bulk_group [%0], [%1], %2;"
                :: "l"(gdst), "r"(saddr), "r"(bytes) : "memory");
            asm volatile("cp.async.bulk.commit_group;" ::: "memory");
            // hold the CTA (and its smem) until the TMA read completes
            asm volatile("cp.async.bulk.wait_group 0;" ::: "memory");
        }
    } else {
        // ---- STG drain: per-warp LDS.128 -> STG.128 (evict-first) ----
        __syncwarp();
        if (warp < rows_here) {
            const float* h = hist[warp];
            float4*       o4 = reinterpret_cast<float4*>(out + (long long)row * VOCAB);
            const float4* h4 = reinterpret_cast<const float4*>(h);
            #pragma unroll
            for (int i = 0; i < 4; ++i)
                __stcs(&o4[i * 32 + lane], h4[i * 32 + lane]);
        }
    }
}

extern "C" void kernel_launch(void* const* d_in, const int* in_sizes, int n_in,
                              void* d_out, int out_size)
{
    const int*   sents   = (const int*)d_in[0];
    const int*   lengths = (const int*)d_in[1];
    const float* alpha   = (const float*)d_in[2];
    float*       out     = (float*)d_out;

    const int nrows = in_sizes[0] / WCHARS;             // B*S = 32768
    const long long main_elems = (long long)nrows * VOCAB;
    const int nlen = in_sizes[1];

    long long extra_ll = (long long)out_size - main_elems;
    if (extra_ll < 0) extra_ll = 0;
    if (extra_ll > WPB * 32) extra_ll = WPB * 32;

    const int blocks = (nrows + WPB - 1) / WPB;
    fofe_kernel<<<blocks, WPB * 32>>>(sents, lengths, alpha, out,
                                      nrows, main_elems, (int)extra_ll, nlen);
}

// round 11
// speedup vs baseline: 1.2909x; 1.0129x over previous
#include <cuda_runtime.h>
#include <stdint.h>

#define VOCAB 512
#define WCHARS 24
#define WPB 16                // rows per block (one warp per row)
#define THREADS (WPB * 32)    // 512

// One warp per (b,s) row, 16 rows per 512-thread block. Histograms live in a
// block-contiguous 32KB smem image of the 16 output rows; ONE 32KB TMA bulk
// copy drains the whole block (fewer, fatter bursts; half the CTA count).
// Tail output (lengths) fused into block 0. int64 inputs arrive as int32
// (jax x64 disabled).
__global__ void __launch_bounds__(THREADS)
fofe_kernel(const int* __restrict__ sents,
            const int* __restrict__ lengths,
            const float* __restrict__ alpha_p,
            float* __restrict__ out,
            int nrows,
            long long main_elems,
            int extra,
            int nlen)
{
    __shared__ __align__(128) float hist[WPB][VOCAB];   // 32 KB

    const int warp = threadIdx.x >> 5;
    const int lane = threadIdx.x & 31;
    const int row0 = blockIdx.x * WPB;
    const int row  = row0 + warp;
    const int rows_here = min(WPB, nrows - row0);

    // fused tail: (out, lengths) second output appended to d_out
    if (blockIdx.x == 0 && (int)threadIdx.x < extra) {
        int i = threadIdx.x;
        out[main_elems + i] = (i < nlen) ? (float)lengths[i] : 0.0f;
    }

    if (warp < rows_here) {
        float* h = hist[warp];

        // input load first; zero-fill overlaps its latency
        int c = 0;
        if (lane < WCHARS)
            c = sents[(long long)row * WCHARS + lane];
        const float a = __ldg(alpha_p);

        // zero the 2KB row histogram: 4 x STS.128 per lane
        float4* h4 = reinterpret_cast<float4*>(h);
        const float4 z = make_float4(0.f, 0.f, 0.f, 0.f);
        #pragma unroll
        for (int j = 0; j < 4; ++j)
            h4[j * 32 + lane] = z;

        const bool valid = (lane < WCHARS) && (c > 0) && (c < VOCAB);
        const unsigned nz = __ballot_sync(0xffffffffu, valid);
        __syncwarp();                       // zeros visible before atomics

        if (valid) {
            const int suffix = __popc(nz & (0xfffffffeu << lane));
            const float w = (suffix == 0) ? 1.0f
                                          : exp2f(log2f(a) * (float)suffix);
            atomicAdd(&h[c], w);            // shared atomic, <=24 per row
        }
    }

    __syncthreads();                        // all 16 histograms complete

    // one elected thread drains the whole 32KB block image via TMA
    if (threadIdx.x == 0) {
        asm volatile("fence.proxy.async.shared::cta;" ::: "memory");
        unsigned saddr = (unsigned)__cvta_generic_to_shared(&hist[0][0]);
        float*   gdst  = out + (long long)row0 * VOCAB;
        unsigned bytes = (unsigned)rows_here * VOCAB * sizeof(float);
        asm volatile(
            "cp.async.bulk.global.shared::cta.bulk_group [%0], [%1], %2;"
            :: "l"(gdst), "r"(saddr), "r"(bytes) : "memory");
        asm volatile("cp.async.bulk.commit_group;" ::: "memory");
        // hold the CTA (and its smem) until the TMA read completes
        asm volatile("cp.async.bulk.wait_group 0;" ::: "memory");
    }
}

extern "C" void kernel_launch(void* const* d_in, const int* in_sizes, int n_in,
                              void* d_out, int out_size)
{
    const int*   sents   = (const int*)d_in[0];
    const int*   lengths = (const int*)d_in[1];
    const float* alpha   = (const float*)d_in[2];
    float*       out     = (float*)d_out;

    const int nrows = in_sizes[0] / WCHARS;             // B*S = 32768
    const long long main_elems = (long long)nrows * VOCAB;
    const int nlen = in_sizes[1];

    long long extra_ll = (long long)out_size - main_elems;
    if (extra_ll < 0) extra_ll = 0;
    if (extra_ll > THREADS) extra_ll = THREADS;

    const int blocks = (nrows + WPB - 1) / WPB;         // 2048
    fofe_kernel<<<blocks, THREADS>>>(sents, lengths, alpha, out,
                                     nrows, main_elems, (int)extra_ll, nlen);
}